// round 14
// baseline (speedup 1.0000x reference)
#include <cuda_runtime.h>

// Problem constants (fixed by the reference)
#define B_N 8192
#define C_N 1000
#define D_N 2048
#define SEP_W 0.001

// ONE WAVE: 256 blocks (512 thr, 2/SM resident -> <=296 slots on 148 SMs).
// X rows: every block handles exactly 32 rows [32b, 32b+32): FIXED trip.
// Center rows: blocks 0..249 handle exactly 4 rows [4b, 4b+4): FIXED trip,
// done BEFORE the x phase; signalers are lowest bids -> wave-1 resident ->
// the epilogue spin always gets released.
#define NBLK 256
#define NCBLK 250
#define CROWS 4             // 250 * 4 = 1000
#define XROWS 32            // 256 * 32 = 8192
#define TPB 512
#define NWARP (TPB / 32)

// Accumulators. Zero-initialized at module load; cl_finalize re-zeroes them
// after consuming, so every graph replay starts from a clean state.
__device__ double   g_sum_xx;         // sum_b ||x_b||^2
__device__ double   g_sum_xc;         // sum_b x_b . c_{label_b}
__device__ double   g_sum_cc;         // sum_b ||c_{label_b}||^2
__device__ double   g_sum_cn;         // sum_c ||c_c||^2
__device__ double   g_cross;          // sum_b dot(x_b, colsum_c)
__device__ float    g_colsum_c[D_N];  // sum_c centers[c,:]
__device__ unsigned g_cdone;          // center-phase blocks completed

// Labels may be int64 (reference asks for it) or int32 (JAX default x64=off).
// For little-endian int64 values < 1000, every odd 32-bit word is 0.
__device__ __forceinline__ int detect_lab64(const int* __restrict__ l) {
    int any = 0;
    #pragma unroll
    for (int k = 0; k < 16; ++k) any |= l[2 * k + 1];
    return any == 0;
}

__device__ __forceinline__ float dot4(float4 a, float4 b) {
    return a.x * b.x + a.y * b.y + a.z * b.z + a.w * b.w;
}

// ---------------------------------------------------------------------------
__global__ void __launch_bounds__(TPB, 2)
cl_main(const float* __restrict__ x,
        const float* __restrict__ centers,
        const int* __restrict__ labels_i32) {
    const int t = threadIdx.x;
    const int lane = t & 31, warp = t >> 5;
    const int bid = blockIdx.x;

    __shared__ float s_red[4][NWARP];
    __shared__ int s_lab[XROWS];

    // ------------- Center phase (blocks 0..NCBLK-1, fixed 4 rows) ---------
    if (bid < NCBLK) {
        const int base = bid * CROWS;
        float4 a0 = make_float4(0.f, 0.f, 0.f, 0.f);
        float cn = 0.f;

        #pragma unroll
        for (int r = 0; r < CROWS; ++r) {
            float4 v = ((const float4*)(centers + (size_t)(base + r) * D_N))[t];
            a0.x += v.x; a0.y += v.y; a0.z += v.z; a0.w += v.w;
            cn += dot4(v, v);
        }

        #pragma unroll
        for (int o = 16; o; o >>= 1)
            cn += __shfl_down_sync(0xffffffffu, cn, o);
        if (lane == 0) s_red[0][warp] = cn;
        __syncthreads();
        if (t == 0) {
            float tcn = 0.f;
            #pragma unroll
            for (int w = 0; w < NWARP; ++w) tcn += s_red[0][w];
            atomicAdd(&g_sum_cn, (double)tcn);
        }
        const int c0i = 4 * t;
        atomicAdd(&g_colsum_c[c0i + 0], a0.x);
        atomicAdd(&g_colsum_c[c0i + 1], a0.y);
        atomicAdd(&g_colsum_c[c0i + 2], a0.z);
        atomicAdd(&g_colsum_c[c0i + 3], a0.w);

        // Signal completion (release) BEFORE starting x streaming.
        __threadfence();
        __syncthreads();
        if (t == 0) atomicAdd(&g_cdone, 1u);
        __syncthreads();
    }

    // ----------------- X phase (ALL blocks, fixed 32 rows) ----------------
    const int base = bid * XROWS;

    // Hoist labels: one load per row, done once, broadcast via shared.
    if (t < XROWS) {
        const int lab64 = detect_lab64(labels_i32);
        const int row = base + t;
        int lab = lab64 ? labels_i32[2 * row] : labels_i32[row];
        s_lab[t] = max(0, min(C_N - 1, lab)); // defensive: never OOB
    }
    __syncthreads();

    float4 ax = make_float4(0.f, 0.f, 0.f, 0.f);
    float xx = 0.f, xc = 0.f, cc = 0.f;

    // Register double-buffer: prefetch row i+1 while accumulating row i.
    float4 v = ((const float4*)(x + (size_t)base * D_N))[t];
    float4 c = ((const float4*)(centers + (size_t)s_lab[0] * D_N))[t];

    #pragma unroll 4
    for (int i = 0; i < XROWS - 1; ++i) {
        float4 vn = ((const float4*)(x + (size_t)(base + i + 1) * D_N))[t];
        float4 cn = ((const float4*)(centers + (size_t)s_lab[i + 1] * D_N))[t];
        ax.x += v.x; ax.y += v.y; ax.z += v.z; ax.w += v.w;
        xx += dot4(v, v);
        xc += dot4(v, c);
        cc += dot4(c, c);
        v = vn; c = cn;
    }
    ax.x += v.x; ax.y += v.y; ax.z += v.z; ax.w += v.w;
    xx += dot4(v, v);
    xc += dot4(v, c);
    cc += dot4(c, c);

    // Wait for all center phases (expected: long finished; zero wait).
    if (t == 0) {
        volatile unsigned* done = &g_cdone;
        while (*done < NCBLK) { __nanosleep(64); }
    }
    __syncthreads();
    __threadfence();   // acquire: colsum_c final

    // Cross contribution from registers: dot(ax, colsum_c[4t..4t+4)).
    const int c0i = 4 * t;
    float4 s4;
    s4.x = __ldcg(&g_colsum_c[c0i + 0]);      // L2 load, bypass L1
    s4.y = __ldcg(&g_colsum_c[c0i + 1]);
    s4.z = __ldcg(&g_colsum_c[c0i + 2]);
    s4.w = __ldcg(&g_colsum_c[c0i + 3]);
    float xs = dot4(ax, s4);

    // One block reduction at the very end.
    #pragma unroll
    for (int o = 16; o; o >>= 1) {
        xx += __shfl_down_sync(0xffffffffu, xx, o);
        xc += __shfl_down_sync(0xffffffffu, xc, o);
        cc += __shfl_down_sync(0xffffffffu, cc, o);
        xs += __shfl_down_sync(0xffffffffu, xs, o);
    }
    if (lane == 0) {
        s_red[0][warp] = xx; s_red[1][warp] = xc;
        s_red[2][warp] = cc; s_red[3][warp] = xs;
    }
    __syncthreads();
    if (t == 0) {
        float txx = 0.f, txc = 0.f, tcc = 0.f, txs = 0.f;
        #pragma unroll
        for (int w = 0; w < NWARP; ++w) {
            txx += s_red[0][w]; txc += s_red[1][w];
            tcc += s_red[2][w]; txs += s_red[3][w];
        }
        atomicAdd(&g_sum_xx, (double)txx);
        atomicAdd(&g_sum_xc, (double)txc);
        atomicAdd(&g_sum_cc, (double)tcc);
        atomicAdd(&g_cross,  (double)txs);
    }
}

// ---------------------------------------------------------------------------
// Finalize: pure scalar combine + reset (colsum reset for next replay).
__global__ void cl_finalize(float* __restrict__ out) {
    const int t = threadIdx.x;

    #pragma unroll
    for (int d = t; d < D_N; d += 256) g_colsum_c[d] = 0.f;

    if (t == 0) {
        const double sum_xx = g_sum_xx;  g_sum_xx = 0.0;
        const double sum_xc = g_sum_xc;  g_sum_xc = 0.0;
        const double sum_cc = g_sum_cc;  g_sum_cc = 0.0;
        const double sum_cn = g_sum_cn;  g_sum_cn = 0.0;
        const double cross  = g_cross;   g_cross  = 0.0;
        g_cdone = 0u;

        // label-path sum (clamp provably inactive: d ~ 4096 >> 1e-12)
        const double label_sum = sum_xx + sum_cc - 2.0 * sum_xc;
        // full distmat sum
        const double total = (double)C_N * sum_xx + (double)B_N * sum_cn - 2.0 * cross;

        const double center_loss = label_sum / (double)B_N;
        const double sep_loss = (total - label_sum) / ((double)B_N * (double)(C_N - 1));
        out[0] = (float)(center_loss - SEP_W * sep_loss);
    }
}

// ---------------------------------------------------------------------------
extern "C" void kernel_launch(void* const* d_in, const int* in_sizes, int n_in,
                              void* d_out, int out_size) {
    const float* x       = (const float*)d_in[0];
    const float* centers = (const float*)d_in[1];
    const int*   labels  = (const int*)d_in[2];
    float* out = (float*)d_out;

    cl_main<<<NBLK, TPB>>>(x, centers, labels);
    cl_finalize<<<1, 256>>>(out);
}

// round 15
// speedup vs baseline: 1.1635x; 1.1635x over previous
#include <cuda_runtime.h>

// Problem constants (fixed by the reference)
#define B_N 8192
#define C_N 1000
#define D_N 2048
#define SEP_W 0.001

// ONE WAVE: 296 blocks = 148 SMs x 2 resident (512 thr, <=64 regs).
// Every block streams x rows [(b*8192)/296, ((b+1)*8192)/296)  (27-28 rows).
// Blocks 0..124 additionally process 8 center rows FIRST and signal BEFORE
// their x phase: signalers are the lowest bids -> wave-1 resident -> the
// epilogue spin always gets released.
// R15 change vs R13: x row loads use __ldcs (evict-first streaming) so the
// 64MB read-once x stream does not evict the 8MB L2-resident centers that
// the dependent gather path needs.
#define NBLK 296
#define NCB 125
#define ROWS_PER_CB 8           // 125 * 8 = 1000
#define TPB 512
#define NWARP (TPB / 32)

// Accumulators. Zero-initialized at module load; cl_finalize re-zeroes them
// after consuming, so every graph replay starts from a clean state.
__device__ double   g_sum_xx;         // sum_b ||x_b||^2
__device__ double   g_sum_xc;         // sum_b x_b . c_{label_b}
__device__ double   g_sum_cc;         // sum_b ||c_{label_b}||^2
__device__ double   g_sum_cn;         // sum_c ||c_c||^2
__device__ double   g_cross;          // sum_b dot(x_b, colsum_c)
__device__ float    g_colsum_c[D_N];  // sum_c centers[c,:]
__device__ unsigned g_cdone;          // center blocks completed

// Labels may be int64 (reference asks for it) or int32 (JAX default x64=off).
// For little-endian int64 values < 1000, every odd 32-bit word is 0.
__device__ __forceinline__ int detect_lab64(const int* __restrict__ l) {
    int any = 0;
    #pragma unroll
    for (int k = 0; k < 16; ++k) any |= l[2 * k + 1];
    return any == 0;
}

__device__ __forceinline__ float dot4(float4 a, float4 b) {
    return a.x * b.x + a.y * b.y + a.z * b.z + a.w * b.w;
}

// ---------------------------------------------------------------------------
__global__ void __launch_bounds__(TPB, 2)
cl_main(const float* __restrict__ x,
        const float* __restrict__ centers,
        const int* __restrict__ labels_i32) {
    const int t = threadIdx.x;
    const int lane = t & 31, warp = t >> 5;
    const int bid = blockIdx.x;

    __shared__ float s_red[4][NWARP];
    __shared__ int s_lab[32];

    // ----------------- Center phase (first NCB blocks only) ---------------
    if (bid < NCB) {
        const int base = bid * ROWS_PER_CB;
        float4 a0 = make_float4(0.f, 0.f, 0.f, 0.f);
        float cn = 0.f;

        #pragma unroll 4
        for (int r = 0; r < ROWS_PER_CB; ++r) {
            float4 v = __ldg((const float4*)(centers + (size_t)(base + r) * D_N) + t);
            a0.x += v.x; a0.y += v.y; a0.z += v.z; a0.w += v.w;
            cn += dot4(v, v);
        }

        #pragma unroll
        for (int o = 16; o; o >>= 1)
            cn += __shfl_down_sync(0xffffffffu, cn, o);
        if (lane == 0) s_red[0][warp] = cn;
        __syncthreads();
        if (t == 0) {
            float tcn = 0.f;
            #pragma unroll
            for (int w = 0; w < NWARP; ++w) tcn += s_red[0][w];
            atomicAdd(&g_sum_cn, (double)tcn);
        }
        const int c0i = 4 * t;
        atomicAdd(&g_colsum_c[c0i + 0], a0.x);
        atomicAdd(&g_colsum_c[c0i + 1], a0.y);
        atomicAdd(&g_colsum_c[c0i + 2], a0.z);
        atomicAdd(&g_colsum_c[c0i + 3], a0.w);

        // Signal completion (release) BEFORE starting x streaming.
        __threadfence();
        __syncthreads();
        if (t == 0) atomicAdd(&g_cdone, 1u);
        __syncthreads();
    }

    // --------------------------- X phase (ALL blocks) ---------------------
    const int xbeg = (bid * B_N) / NBLK;
    const int xend = ((bid + 1) * B_N) / NBLK;
    const int nrows = xend - xbeg;            // 27 or 28

    // Hoist labels: one load per row, done once, broadcast via shared.
    if (t < nrows) {
        const int lab64 = detect_lab64(labels_i32);
        const int row = xbeg + t;
        int lab = lab64 ? labels_i32[2 * row] : labels_i32[row];
        s_lab[t] = max(0, min(C_N - 1, lab)); // defensive: never OOB
    }
    __syncthreads();

    float4 ax = make_float4(0.f, 0.f, 0.f, 0.f);
    float xx = 0.f, xc = 0.f, cc = 0.f;

    #pragma unroll 4
    for (int i = 0; i < nrows; ++i) {
        const int row = xbeg + i;
        const int lab = s_lab[i];
        // x: read-once stream -> evict-first, keep centers resident in L2.
        float4 v = __ldcs((const float4*)(x + (size_t)row * D_N) + t);
        float4 c = __ldg((const float4*)(centers + (size_t)lab * D_N) + t);
        ax.x += v.x; ax.y += v.y; ax.z += v.z; ax.w += v.w;
        xx += dot4(v, v);
        xc += dot4(v, c);
        cc += dot4(c, c);
    }

    // Wait for all center phases (expected: long finished; zero wait).
    if (t == 0) {
        volatile unsigned* done = &g_cdone;
        while (*done < NCB) { __nanosleep(64); }
    }
    __syncthreads();
    __threadfence();   // acquire: colsum_c final

    // Cross contribution from registers: dot(ax, colsum_c[4t..4t+4)).
    const int c0i = 4 * t;
    float4 s4;
    s4.x = __ldcg(&g_colsum_c[c0i + 0]);      // L2 load, bypass L1
    s4.y = __ldcg(&g_colsum_c[c0i + 1]);
    s4.z = __ldcg(&g_colsum_c[c0i + 2]);
    s4.w = __ldcg(&g_colsum_c[c0i + 3]);
    float xs = dot4(ax, s4);

    // One block reduction at the very end.
    #pragma unroll
    for (int o = 16; o; o >>= 1) {
        xx += __shfl_down_sync(0xffffffffu, xx, o);
        xc += __shfl_down_sync(0xffffffffu, xc, o);
        cc += __shfl_down_sync(0xffffffffu, cc, o);
        xs += __shfl_down_sync(0xffffffffu, xs, o);
    }
    if (lane == 0) {
        s_red[0][warp] = xx; s_red[1][warp] = xc;
        s_red[2][warp] = cc; s_red[3][warp] = xs;
    }
    __syncthreads();
    if (t == 0) {
        float txx = 0.f, txc = 0.f, tcc = 0.f, txs = 0.f;
        #pragma unroll
        for (int w = 0; w < NWARP; ++w) {
            txx += s_red[0][w]; txc += s_red[1][w];
            tcc += s_red[2][w]; txs += s_red[3][w];
        }
        atomicAdd(&g_sum_xx, (double)txx);
        atomicAdd(&g_sum_xc, (double)txc);
        atomicAdd(&g_sum_cc, (double)tcc);
        atomicAdd(&g_cross,  (double)txs);
    }
}

// ---------------------------------------------------------------------------
// Finalize: pure scalar combine + reset (colsum reset for next replay).
__global__ void cl_finalize(float* __restrict__ out) {
    const int t = threadIdx.x;

    #pragma unroll
    for (int d = t; d < D_N; d += 256) g_colsum_c[d] = 0.f;

    if (t == 0) {
        const double sum_xx = g_sum_xx;  g_sum_xx = 0.0;
        const double sum_xc = g_sum_xc;  g_sum_xc = 0.0;
        const double sum_cc = g_sum_cc;  g_sum_cc = 0.0;
        const double sum_cn = g_sum_cn;  g_sum_cn = 0.0;
        const double cross  = g_cross;   g_cross  = 0.0;
        g_cdone = 0u;

        // label-path sum (clamp provably inactive: d ~ 4096 >> 1e-12)
        const double label_sum = sum_xx + sum_cc - 2.0 * sum_xc;
        // full distmat sum
        const double total = (double)C_N * sum_xx + (double)B_N * sum_cn - 2.0 * cross;

        const double center_loss = label_sum / (double)B_N;
        const double sep_loss = (total - label_sum) / ((double)B_N * (double)(C_N - 1));
        out[0] = (float)(center_loss - SEP_W * sep_loss);
    }
}

// ---------------------------------------------------------------------------
extern "C" void kernel_launch(void* const* d_in, const int* in_sizes, int n_in,
                              void* d_out, int out_size) {
    const float* x       = (const float*)d_in[0];
    const float* centers = (const float*)d_in[1];
    const int*   labels  = (const int*)d_in[2];
    float* out = (float*)d_out;

    cl_main<<<NBLK, TPB>>>(x, centers, labels);
    cl_finalize<<<1, 256>>>(out);
}